// round 16
// baseline (speedup 1.0000x reference)
#include <cuda_runtime.h>
#include <cuda_fp16.h>
#include <cstdint>

// ---------------------------------------------------------------------------
// GATv2 collapsed:
//   out[e] = leaky_relu( P[src[e]] + Q[dst[e]] ) . w2 + b2
//   PQ = node_feat @ Wc + bc,  Wc = [W_node; b_node] @ W_a1 (biases folded)
// Node path = r11 proven: build_wc (FFMA tiled) + sgemm_tc (tf32 m16n8k8).
// Edge: MLP-8 gather + packed f32x2 FMA dot.
// ---------------------------------------------------------------------------

#define CH 128
#define MAX_NODES 10240
#define MAX_K 128

__device__ __half g_PQh[MAX_NODES * 2 * CH];   // per node: [P(128) | Q(128)] fp16
__device__ float  g_Wc[MAX_K * 2 * CH];        // combined weight [K, 256]
__device__ float  g_bc[2 * CH];                // combined bias   [256]

__device__ __forceinline__ unsigned int f32_to_tf32(float f) {
    unsigned int r;
    asm("cvt.rna.tf32.f32 %0, %1;" : "=r"(r) : "f"(f));
    return r;
}

__device__ __forceinline__ void mma_tf32_16x8x8(
    float& d0, float& d1, float& d2, float& d3,
    unsigned int a0, unsigned int a1, unsigned int a2, unsigned int a3,
    unsigned int b0, unsigned int b1) {
    asm volatile(
        "mma.sync.aligned.m16n8k8.row.col.f32.tf32.tf32.f32 "
        "{%0,%1,%2,%3}, {%4,%5,%6,%7}, {%8,%9}, {%0,%1,%2,%3};"
        : "+f"(d0), "+f"(d1), "+f"(d2), "+f"(d3)
        : "r"(a0), "r"(a1), "r"(a2), "r"(a3), "r"(b0), "r"(b1));
}

__device__ __forceinline__ void fma_f32x2(unsigned long long& d,
                                          unsigned long long a,
                                          unsigned long long b,
                                          unsigned long long c) {
    asm("fma.rn.f32x2 %0, %1, %2, %3;" : "=l"(d) : "l"(a), "l"(b), "l"(c));
}
__device__ __forceinline__ unsigned long long pack_f32x2(float lo, float hi) {
    unsigned long long r;
    asm("mov.b64 %0, {%1, %2};" : "=l"(r) : "r"(__float_as_uint(lo)), "r"(__float_as_uint(hi)));
    return r;
}
__device__ __forceinline__ void unpack_f32x2(unsigned long long v, float& lo, float& hi) {
    unsigned int a, b;
    asm("mov.b64 {%0, %1}, %2;" : "=r"(a), "=r"(b) : "l"(v));
    lo = __uint_as_float(a);
    hi = __uint_as_float(b);
}

// ---------------------------------------------------------------------------
// Kernel 1 (proven r5/r11): Wc[119x256] = [W_node; b_node] @ W_a1-half.
// ---------------------------------------------------------------------------
__global__ __launch_bounds__(256) void build_wc_kernel(
    const float* __restrict__ W_node,   // [K,128]
    const float* __restrict__ b_node,   // [128]
    const float* __restrict__ W_a1,     // [256,128]
    const float* __restrict__ b_a1,     // [128]
    int K) {
    __shared__ __align__(16) float As[32][128];
    __shared__ __align__(16) float Bs[128][16];

    int tid   = threadIdx.x;
    int kbase = blockIdx.x * 32;
    int jbase = blockIdx.y * 16;
    int half  = jbase >> 7;
    int jloc  = jbase & (CH - 1);

#pragma unroll
    for (int i = 0; i < 4; i++) {
        int id = tid + i * 256;
        int r  = id >> 5;
        int c4 = id & 31;
        int k  = kbase + r;
        float4 v = make_float4(0.f, 0.f, 0.f, 0.f);
        if (k < K)       v = ((const float4*)(W_node + (size_t)k * CH))[c4];
        else if (k == K) v = ((const float4*)b_node)[c4];
        *(float4*)&As[r][c4 * 4] = v;
    }
#pragma unroll
    for (int i = 0; i < 2; i++) {
        int id = tid + i * 256;
        int c  = id >> 2;
        int j4 = id & 3;
        float4 v = ((const float4*)(W_a1 + (size_t)(half * CH + c) * CH + jloc))[j4];
        *(float4*)&Bs[c][j4 * 4] = v;
    }
    __syncthreads();

    int c1 = tid & 15;
    int r1 = tid >> 4;
    float acc0 = 0.f, acc1 = 0.f;
#pragma unroll 8
    for (int k = 0; k < 128; k++) {
        float b0 = Bs[k][c1];
        acc0 = fmaf(As[r1][k],      b0, acc0);
        acc1 = fmaf(As[r1 + 16][k], b0, acc1);
    }

    int jj = jbase + c1;
#pragma unroll
    for (int i = 0; i < 2; i++) {
        int k = kbase + r1 + 16 * i;
        float a = (i == 0) ? acc0 : acc1;
        if (k < K) {
            g_Wc[(size_t)k * (2 * CH) + jj] = a;
        } else if (k == K) {
            g_bc[jj] = a + (half ? b_a1[jj - CH] : 0.f);
        }
    }
}

// ---------------------------------------------------------------------------
// Kernel 2 (proven r11): tensor-core SGEMM  PQ = node_feat @ g_Wc + g_bc -> fp16
// tf32 mma.sync.m16n8k8. Block 128x128, 8 warps (4M x 2N), warp 32x64.
// ---------------------------------------------------------------------------
__global__ __launch_bounds__(256) void sgemm_tc_kernel(
    const float* __restrict__ A, int M, int K) {
    const int N = 2 * CH;
    __shared__ unsigned int As[128][20];
    __shared__ unsigned int Bs[16][136];

    int tid  = threadIdx.x;
    int brow = blockIdx.x * 128;
    int bcol = blockIdx.y * 128;

    int w    = tid >> 5;
    int lane = tid & 31;
    int wm   = w & 3;
    int wn   = w >> 2;
    int g    = lane >> 2;
    int tg   = lane & 3;

    float acc[2][8][4];
#pragma unroll
    for (int i = 0; i < 2; i++)
#pragma unroll
        for (int j = 0; j < 8; j++)
#pragma unroll
            for (int c = 0; c < 4; c++) acc[i][j][c] = 0.f;

    for (int k0 = 0; k0 < K; k0 += 16) {
#pragma unroll
        for (int i = 0; i < 8; i++) {
            int id = tid + i * 256;
            int r  = id >> 4;
            int k  = id & 15;
            int m  = brow + r;
            float v = 0.f;
            if (m < M && (k0 + k) < K) v = A[(size_t)m * K + k0 + k];
            As[r][k] = f32_to_tf32(v);
        }
#pragma unroll
        for (int i = 0; i < 8; i++) {
            int id = tid + i * 256;
            int k  = id >> 7;
            int n  = id & 127;
            float v = 0.f;
            if ((k0 + k) < K) v = g_Wc[(size_t)(k0 + k) * N + bcol + n];
            Bs[k][n] = f32_to_tf32(v);
        }
        __syncthreads();

#pragma unroll
        for (int ks = 0; ks < 2; ks++) {
            int kb = ks * 8;
            unsigned int af[2][4];
#pragma unroll
            for (int mt = 0; mt < 2; mt++) {
                int r0 = wm * 32 + mt * 16;
                af[mt][0] = As[r0 + g][kb + tg];
                af[mt][1] = As[r0 + g + 8][kb + tg];
                af[mt][2] = As[r0 + g][kb + tg + 4];
                af[mt][3] = As[r0 + g + 8][kb + tg + 4];
            }
#pragma unroll
            for (int nt = 0; nt < 8; nt++) {
                int n0 = wn * 64 + nt * 8;
                unsigned int b0 = Bs[kb + tg][n0 + g];
                unsigned int b1 = Bs[kb + tg + 4][n0 + g];
#pragma unroll
                for (int mt = 0; mt < 2; mt++) {
                    mma_tf32_16x8x8(acc[mt][nt][0], acc[mt][nt][1],
                                    acc[mt][nt][2], acc[mt][nt][3],
                                    af[mt][0], af[mt][1], af[mt][2], af[mt][3],
                                    b0, b1);
                }
            }
        }
        __syncthreads();
    }

#pragma unroll
    for (int mt = 0; mt < 2; mt++) {
#pragma unroll
        for (int nt = 0; nt < 8; nt++) {
            int col  = bcol + wn * 64 + nt * 8 + tg * 2;
            float b0 = g_bc[col];
            float b1 = g_bc[col + 1];
            int row0 = brow + wm * 32 + mt * 16 + g;
            int row1 = row0 + 8;
            if (row0 < M) {
                __half2 h = __floats2half2_rn(acc[mt][nt][0] + b0,
                                              acc[mt][nt][1] + b1);
                *(__half2*)&g_PQh[(size_t)row0 * N + col] = h;
            }
            if (row1 < M) {
                __half2 h = __floats2half2_rn(acc[mt][nt][2] + b0,
                                              acc[mt][nt][3] + b1);
                *(__half2*)&g_PQh[(size_t)row1 * N + col] = h;
            }
        }
    }
}

// ---------------------------------------------------------------------------
// Kernel 3: 16 lanes/edge, 8 edges per warp, MLP 8 (proven memory pattern),
// dot via packed f32x2 FMA (half the FFMA issue slots).
// ---------------------------------------------------------------------------
__global__ __launch_bounds__(256) void edge_kernel(
    const int* __restrict__ src, const int* __restrict__ dst,
    const float* __restrict__ W_a2,   // [128]
    const float* __restrict__ b_a2,   // [1]
    float* __restrict__ out, int E) {
    int gwarp = (blockIdx.x * blockDim.x + threadIdx.x) >> 5;
    int lane  = threadIdx.x & 31;
    int sub   = lane & 15;
    int hw    = lane >> 4;

    int eb = gwarp * 8 + hw;

    int  ee[4];
    bool vv[4];
#pragma unroll
    for (int j = 0; j < 4; j++) {
        ee[j] = eb + 2 * j;
        vv[j] = (ee[j] < E);
    }

    int sidx[4], didx[4];
#pragma unroll
    for (int j = 0; j < 4; j++) {
        int ec  = vv[j] ? ee[j] : 0;
        sidx[j] = src[ec];
        didx[j] = dst[ec];
    }

    const uint4* PQ = (const uint4*)g_PQh;
    uint4 pv[4], qv[4];
#pragma unroll
    for (int j = 0; j < 4; j++) {
        pv[j] = PQ[(size_t)sidx[j] * 32 + sub];
        qv[j] = PQ[(size_t)didx[j] * 32 + 16 + sub];
    }

    float4 w0 = ((const float4*)W_a2)[sub * 2];
    float4 w1 = ((const float4*)W_a2)[sub * 2 + 1];
    unsigned long long w64[4];
    w64[0] = pack_f32x2(w0.x, w0.y);
    w64[1] = pack_f32x2(w0.z, w0.w);
    w64[2] = pack_f32x2(w1.x, w1.y);
    w64[3] = pack_f32x2(w1.z, w1.w);

    const __half2 slope = __float2half2_rn(0.01f);

    unsigned long long acc64[4] = {0ull, 0ull, 0ull, 0ull};
#pragma unroll
    for (int j = 0; j < 4; j++) {
        const __half2* ph = (const __half2*)&pv[j];
        const __half2* qh = (const __half2*)&qv[j];
#pragma unroll
        for (int i = 0; i < 4; i++) {
            __half2 x = __hadd2(ph[i], qh[i]);
            x = __hmax2(x, __hmul2(x, slope));          // leaky_relu
            float2 f = __half22float2(x);
            fma_f32x2(acc64[j], pack_f32x2(f.x, f.y), w64[i], acc64[j]);
        }
    }

    float acc[4];
#pragma unroll
    for (int j = 0; j < 4; j++) {
        float lo, hi;
        unpack_f32x2(acc64[j], lo, hi);
        acc[j] = lo + hi;
    }
#pragma unroll
    for (int off = 8; off; off >>= 1) {
#pragma unroll
        for (int j = 0; j < 4; j++)
            acc[j] += __shfl_xor_sync(0xFFFFFFFFu, acc[j], off);
    }

    if (sub == 0) {
        float b2 = b_a2[0];
#pragma unroll
        for (int j = 0; j < 4; j++)
            if (vv[j]) out[ee[j]] = acc[j] + b2;
    }
}

// ---------------------------------------------------------------------------
extern "C" void kernel_launch(void* const* d_in, const int* in_sizes, int n_in,
                              void* d_out, int out_size) {
    const float* node_feat = (const float*)d_in[0];
    const int*   src       = (const int*)  d_in[2];
    const int*   dst       = (const int*)  d_in[3];
    const float* W_node    = (const float*)d_in[4];
    const float* b_node    = (const float*)d_in[5];
    const float* W_a1      = (const float*)d_in[8];
    const float* b_a1      = (const float*)d_in[9];
    const float* W_a2      = (const float*)d_in[10];
    const float* b_a2      = (const float*)d_in[11];
    float* out = (float*)d_out;

    int E = in_sizes[2];
    int K = in_sizes[4] / CH;        // 118
    int M = in_sizes[0] / K;         // 10000

    {
        dim3 g((K + 1 + 31) / 32, 16);
        build_wc_kernel<<<g, 256>>>(W_node, b_node, W_a1, b_a1, K);
    }
    {
        dim3 g((M + 127) / 128, 2);
        sgemm_tc_kernel<<<g, 256>>>(node_feat, M, K);
    }
    {
        int nwarps = (E + 7) / 8;               // 8 edges per warp
        int blocks = (nwarps * 32 + 255) / 256;
        edge_kernel<<<blocks, 256>>>(src, dst, W_a2, b_a2, out, E);
    }
}

// round 17
// speedup vs baseline: 1.1820x; 1.1820x over previous
#include <cuda_runtime.h>
#include <cuda_fp16.h>
#include <cstdint>

// ---------------------------------------------------------------------------
// GATv2 collapsed:
//   out[e] = leaky_relu( P[src[e]] + Q[dst[e]] ) . w2 + b2
//   PQ = node_feat @ Wc + bc,  Wc = [W_node; b_node] @ W_a1 (biases folded)
// build_wc on tensor cores (tf32), sgemm_tc r11-proven, edge r10-proven.
// ---------------------------------------------------------------------------

#define CH 128
#define MAX_NODES 10240
#define MAX_K 128

__device__ __half g_PQh[MAX_NODES * 2 * CH];   // per node: [P(128) | Q(128)] fp16
__device__ float  g_Wc[MAX_K * 2 * CH];        // combined weight [K, 256]
__device__ float  g_bc[2 * CH];                // combined bias   [256]

__device__ __forceinline__ unsigned int f32_to_tf32(float f) {
    unsigned int r;
    asm("cvt.rna.tf32.f32 %0, %1;" : "=r"(r) : "f"(f));
    return r;
}

__device__ __forceinline__ void mma_tf32_16x8x8(
    float& d0, float& d1, float& d2, float& d3,
    unsigned int a0, unsigned int a1, unsigned int a2, unsigned int a3,
    unsigned int b0, unsigned int b1) {
    asm volatile(
        "mma.sync.aligned.m16n8k8.row.col.f32.tf32.tf32.f32 "
        "{%0,%1,%2,%3}, {%4,%5,%6,%7}, {%8,%9}, {%0,%1,%2,%3};"
        : "+f"(d0), "+f"(d1), "+f"(d2), "+f"(d3)
        : "r"(a0), "r"(a1), "r"(a2), "r"(a3), "r"(b0), "r"(b1));
}

// ---------------------------------------------------------------------------
// Kernel 1: Wc[119x256] = [W_node; b_node] @ W_a1 on tensor cores.
// 4 blocks: blockIdx.x -> half (0/1) x 64-col slice. M-tile 128 (rows>=119
// zero-padded), K=128 contraction. 8 warps as 4M x 2N, warp tile 32x32.
// ---------------------------------------------------------------------------
__global__ __launch_bounds__(256) void build_wc_tc_kernel(
    const float* __restrict__ W_node,   // [K,128]
    const float* __restrict__ b_node,   // [128]
    const float* __restrict__ W_a1,     // [256,128]
    const float* __restrict__ b_a1,     // [128]
    int K) {
    __shared__ unsigned int As[128][20];
    __shared__ unsigned int Bs[16][72];

    int tid  = threadIdx.x;
    int half = blockIdx.x >> 1;
    int jloc = (blockIdx.x & 1) * 64;

    int w    = tid >> 5;
    int lane = tid & 31;
    int wm   = w & 3;            // M offset wm*32
    int wn   = w >> 2;           // N offset wn*32
    int g    = lane >> 2;
    int tg   = lane & 3;

    float acc[2][4][4];
#pragma unroll
    for (int i = 0; i < 2; i++)
#pragma unroll
        for (int j = 0; j < 4; j++)
#pragma unroll
            for (int c = 0; c < 4; c++) acc[i][j][c] = 0.f;

    for (int k0 = 0; k0 < CH; k0 += 16) {
        // A rows = Wc k-rows: W_node rows, row K = b_node, rows > K = 0.
#pragma unroll
        for (int i = 0; i < 8; i++) {
            int id = tid + i * 256;
            int r  = id >> 4;
            int k  = id & 15;
            float v = 0.f;
            if (r < K)       v = W_node[(size_t)r * CH + k0 + k];
            else if (r == K) v = b_node[k0 + k];
            As[r][k] = f32_to_tf32(v);
        }
        // B = W_a1 rows (contraction) x 64-col slice.
#pragma unroll
        for (int i = 0; i < 4; i++) {
            int id = tid + i * 256;
            int k  = id >> 6;            // 0..15
            int n  = id & 63;
            float v = W_a1[(size_t)(half * CH + k0 + k) * CH + jloc + n];
            Bs[k][n] = f32_to_tf32(v);
        }
        __syncthreads();

#pragma unroll
        for (int ks = 0; ks < 2; ks++) {
            int kb = ks * 8;
            unsigned int af[2][4];
#pragma unroll
            for (int mt = 0; mt < 2; mt++) {
                int r0 = wm * 32 + mt * 16;
                af[mt][0] = As[r0 + g][kb + tg];
                af[mt][1] = As[r0 + g + 8][kb + tg];
                af[mt][2] = As[r0 + g][kb + tg + 4];
                af[mt][3] = As[r0 + g + 8][kb + tg + 4];
            }
#pragma unroll
            for (int nt = 0; nt < 4; nt++) {
                int n0 = wn * 32 + nt * 8;
                unsigned int b0 = Bs[kb + tg][n0 + g];
                unsigned int b1 = Bs[kb + tg + 4][n0 + g];
#pragma unroll
                for (int mt = 0; mt < 2; mt++) {
                    mma_tf32_16x8x8(acc[mt][nt][0], acc[mt][nt][1],
                                    acc[mt][nt][2], acc[mt][nt][3],
                                    af[mt][0], af[mt][1], af[mt][2], af[mt][3],
                                    b0, b1);
                }
            }
        }
        __syncthreads();
    }

#pragma unroll
    for (int mt = 0; mt < 2; mt++) {
#pragma unroll
        for (int nt = 0; nt < 4; nt++) {
            int nloc  = wn * 32 + nt * 8 + tg * 2;
            int jglob = half * CH + jloc + nloc;
            int kr0   = wm * 32 + mt * 16 + g;
            int kr1   = kr0 + 8;
            if (kr0 < K) {
                g_Wc[(size_t)kr0 * (2 * CH) + jglob]     = acc[mt][nt][0];
                g_Wc[(size_t)kr0 * (2 * CH) + jglob + 1] = acc[mt][nt][1];
            } else if (kr0 == K) {
                g_bc[jglob]     = acc[mt][nt][0] + (half ? b_a1[jglob - CH]     : 0.f);
                g_bc[jglob + 1] = acc[mt][nt][1] + (half ? b_a1[jglob + 1 - CH] : 0.f);
            }
            if (kr1 < K) {
                g_Wc[(size_t)kr1 * (2 * CH) + jglob]     = acc[mt][nt][2];
                g_Wc[(size_t)kr1 * (2 * CH) + jglob + 1] = acc[mt][nt][3];
            } else if (kr1 == K) {
                g_bc[jglob]     = acc[mt][nt][2] + (half ? b_a1[jglob - CH]     : 0.f);
                g_bc[jglob + 1] = acc[mt][nt][3] + (half ? b_a1[jglob + 1 - CH] : 0.f);
            }
        }
    }
}

// ---------------------------------------------------------------------------
// Kernel 2 (proven r11): tensor-core SGEMM  PQ = node_feat @ g_Wc + g_bc -> fp16
// ---------------------------------------------------------------------------
__global__ __launch_bounds__(256) void sgemm_tc_kernel(
    const float* __restrict__ A, int M, int K) {
    const int N = 2 * CH;
    __shared__ unsigned int As[128][20];
    __shared__ unsigned int Bs[16][136];

    int tid  = threadIdx.x;
    int brow = blockIdx.x * 128;
    int bcol = blockIdx.y * 128;

    int w    = tid >> 5;
    int lane = tid & 31;
    int wm   = w & 3;
    int wn   = w >> 2;
    int g    = lane >> 2;
    int tg   = lane & 3;

    float acc[2][8][4];
#pragma unroll
    for (int i = 0; i < 2; i++)
#pragma unroll
        for (int j = 0; j < 8; j++)
#pragma unroll
            for (int c = 0; c < 4; c++) acc[i][j][c] = 0.f;

    for (int k0 = 0; k0 < K; k0 += 16) {
#pragma unroll
        for (int i = 0; i < 8; i++) {
            int id = tid + i * 256;
            int r  = id >> 4;
            int k  = id & 15;
            int m  = brow + r;
            float v = 0.f;
            if (m < M && (k0 + k) < K) v = A[(size_t)m * K + k0 + k];
            As[r][k] = f32_to_tf32(v);
        }
#pragma unroll
        for (int i = 0; i < 8; i++) {
            int id = tid + i * 256;
            int k  = id >> 7;
            int n  = id & 127;
            float v = 0.f;
            if ((k0 + k) < K) v = g_Wc[(size_t)(k0 + k) * N + bcol + n];
            Bs[k][n] = f32_to_tf32(v);
        }
        __syncthreads();

#pragma unroll
        for (int ks = 0; ks < 2; ks++) {
            int kb = ks * 8;
            unsigned int af[2][4];
#pragma unroll
            for (int mt = 0; mt < 2; mt++) {
                int r0 = wm * 32 + mt * 16;
                af[mt][0] = As[r0 + g][kb + tg];
                af[mt][1] = As[r0 + g + 8][kb + tg];
                af[mt][2] = As[r0 + g][kb + tg + 4];
                af[mt][3] = As[r0 + g + 8][kb + tg + 4];
            }
#pragma unroll
            for (int nt = 0; nt < 8; nt++) {
                int n0 = wn * 64 + nt * 8;
                unsigned int b0 = Bs[kb + tg][n0 + g];
                unsigned int b1 = Bs[kb + tg + 4][n0 + g];
#pragma unroll
                for (int mt = 0; mt < 2; mt++) {
                    mma_tf32_16x8x8(acc[mt][nt][0], acc[mt][nt][1],
                                    acc[mt][nt][2], acc[mt][nt][3],
                                    af[mt][0], af[mt][1], af[mt][2], af[mt][3],
                                    b0, b1);
                }
            }
        }
        __syncthreads();
    }

#pragma unroll
    for (int mt = 0; mt < 2; mt++) {
#pragma unroll
        for (int nt = 0; nt < 8; nt++) {
            int col  = bcol + wn * 64 + nt * 8 + tg * 2;
            float b0 = g_bc[col];
            float b1 = g_bc[col + 1];
            int row0 = brow + wm * 32 + mt * 16 + g;
            int row1 = row0 + 8;
            if (row0 < M) {
                __half2 h = __floats2half2_rn(acc[mt][nt][0] + b0,
                                              acc[mt][nt][1] + b1);
                *(__half2*)&g_PQh[(size_t)row0 * N + col] = h;
            }
            if (row1 < M) {
                __half2 h = __floats2half2_rn(acc[mt][nt][2] + b0,
                                              acc[mt][nt][3] + b1);
                *(__half2*)&g_PQh[(size_t)row1 * N + col] = h;
            }
        }
    }
}

// ---------------------------------------------------------------------------
// Kernel 3 (proven r10, untouched): 16 lanes/edge, 8 edges/warp, MLP 8.
// ---------------------------------------------------------------------------
__global__ __launch_bounds__(256) void edge_kernel(
    const int* __restrict__ src, const int* __restrict__ dst,
    const float* __restrict__ W_a2,   // [128]
    const float* __restrict__ b_a2,   // [1]
    float* __restrict__ out, int E) {
    int gwarp = (blockIdx.x * blockDim.x + threadIdx.x) >> 5;
    int lane  = threadIdx.x & 31;
    int sub   = lane & 15;
    int hw    = lane >> 4;

    int eb = gwarp * 8 + hw;

    int  ee[4];
    bool vv[4];
#pragma unroll
    for (int j = 0; j < 4; j++) {
        ee[j] = eb + 2 * j;
        vv[j] = (ee[j] < E);
    }

    int sidx[4], didx[4];
#pragma unroll
    for (int j = 0; j < 4; j++) {
        int ec  = vv[j] ? ee[j] : 0;
        sidx[j] = src[ec];
        didx[j] = dst[ec];
    }

    const uint4* PQ = (const uint4*)g_PQh;
    uint4 pv[4], qv[4];
#pragma unroll
    for (int j = 0; j < 4; j++) {
        pv[j] = PQ[(size_t)sidx[j] * 32 + sub];
        qv[j] = PQ[(size_t)didx[j] * 32 + 16 + sub];
    }

    float4 w0 = ((const float4*)W_a2)[sub * 2];
    float4 w1 = ((const float4*)W_a2)[sub * 2 + 1];
    float wv[8] = {w0.x, w0.y, w0.z, w0.w, w1.x, w1.y, w1.z, w1.w};

    const __half2 slope = __float2half2_rn(0.01f);

    float acc[4] = {0.f, 0.f, 0.f, 0.f};
#pragma unroll
    for (int j = 0; j < 4; j++) {
        const __half2* ph = (const __half2*)&pv[j];
        const __half2* qh = (const __half2*)&qv[j];
#pragma unroll
        for (int i = 0; i < 4; i++) {
            __half2 x = __hadd2(ph[i], qh[i]);
            x = __hmax2(x, __hmul2(x, slope));
            float2 f = __half22float2(x);
            acc[j] = fmaf(f.x, wv[2 * i],     acc[j]);
            acc[j] = fmaf(f.y, wv[2 * i + 1], acc[j]);
        }
    }
#pragma unroll
    for (int off = 8; off; off >>= 1) {
#pragma unroll
        for (int j = 0; j < 4; j++)
            acc[j] += __shfl_xor_sync(0xFFFFFFFFu, acc[j], off);
    }

    if (sub == 0) {
        float b2 = b_a2[0];
#pragma unroll
        for (int j = 0; j < 4; j++)
            if (vv[j]) out[ee[j]] = acc[j] + b2;
    }
}

// ---------------------------------------------------------------------------
extern "C" void kernel_launch(void* const* d_in, const int* in_sizes, int n_in,
                              void* d_out, int out_size) {
    const float* node_feat = (const float*)d_in[0];
    const int*   src       = (const int*)  d_in[2];
    const int*   dst       = (const int*)  d_in[3];
    const float* W_node    = (const float*)d_in[4];
    const float* b_node    = (const float*)d_in[5];
    const float* W_a1      = (const float*)d_in[8];
    const float* b_a1      = (const float*)d_in[9];
    const float* W_a2      = (const float*)d_in[10];
    const float* b_a2      = (const float*)d_in[11];
    float* out = (float*)d_out;

    int E = in_sizes[2];
    int K = in_sizes[4] / CH;        // 118
    int M = in_sizes[0] / K;         // 10000

    build_wc_tc_kernel<<<4, 256>>>(W_node, b_node, W_a1, b_a1, K);
    {
        dim3 g((M + 127) / 128, 2);
        sgemm_tc_kernel<<<g, 256>>>(node_feat, M, K);
    }
    {
        int nwarps = (E + 7) / 8;               // 8 edges per warp
        int blocks = (nwarps * 32 + 255) / 256;
        edge_kernel<<<blocks, 256>>>(src, dst, W_a2, b_a2, out, E);
    }
}